// round 7
// baseline (speedup 1.0000x reference)
#include <cuda_runtime.h>
#include <cstdint>

// out[row, :] = features[rules[row], :]
// features: [N_ACTIVE=200000, C=64] fp32   (51.2 MB — resident in 126 MB L2)
// rules:    [N_ROWS=524288] int32
// out:      [N_ROWS, 64] fp32
//
// R4 -> R5: still latency-bound (DRAM 50%, issue 15%, nothing at ceiling).
//  - ILP 4 -> 8: ~2x outstanding gathers per warp (net in-flight rises even
//    though occupancy drops on register pressure)
//  - keep __stcs streaming stores (verified: DRAM traffic == output stream only,
//    gathers are L2 hits)

#define ILP 8

__global__ void __launch_bounds__(256)
bl_gather_kernel(const float4* __restrict__ feat,
                 const int* __restrict__ rules,
                 float4* __restrict__ out,
                 int total_vec4)  // n_rows * 16
{
    const int tid    = blockIdx.x * blockDim.x + threadIdx.x;
    const int stride = gridDim.x * blockDim.x;

    int    idx[ILP];
    int    r[ILP];
    float4 v[ILP];

    // index loads: coalesced, broadcast within 16-thread groups
    #pragma unroll
    for (int i = 0; i < ILP; i++) {
        idx[i] = tid + i * stride;
        int row = idx[i] >> 4;
        r[i] = (idx[i] < total_vec4) ? __ldg(&rules[row]) : 0;
    }
    // gather phase: ILP independent 128-bit loads in flight
    #pragma unroll
    for (int i = 0; i < ILP; i++) {
        int c4 = idx[i] & 15;
        if (idx[i] < total_vec4)
            v[i] = __ldg(&feat[(long long)r[i] * 16 + c4]);
    }
    // store phase: streaming (evict-first) protects feature residency in L2
    #pragma unroll
    for (int i = 0; i < ILP; i++) {
        if (idx[i] < total_vec4)
            __stcs(&out[idx[i]], v[i]);
    }
}

extern "C" void kernel_launch(void* const* d_in, const int* in_sizes, int n_in,
                              void* d_out, int out_size)
{
    const float4* feat  = (const float4*)d_in[0];   // features [nActive, 64] fp32
    const int*    rules = (const int*)d_in[1];      // rules [n_rows] int32

    int n_rows     = in_sizes[1];          // 524288
    int total_vec4 = n_rows * 16;          // 8,388,608

    float4* out = (float4*)d_out;

    const int threads = 256;
    int blocks = (total_vec4 + threads * ILP - 1) / (threads * ILP);  // 4096
    bl_gather_kernel<<<blocks, threads>>>(feat, rules, out, total_vec4);
}